// round 1
// baseline (speedup 1.0000x reference)
#include <cuda_runtime.h>
#include <math.h>

// Problem constants (fixed shapes)
#define NN 100000
#define EE 3200000
#define FF 13
#define HH 64
#define GG 512
#define NCLS 2
#define BN_EPS 1e-5f

// -------- scratch (no allocation allowed: __device__ globals) --------
__device__ float g_x16 [NN * 16];  // padded input features (read-only during edge pass 1)
__device__ float g_agg1[NN * 16];  // layer-1 aggregate (x + sum neighbors), padded
__device__ float g_agg [NN * 64];  // layer-2/3 aggregate buffer
__device__ float g_h1  [NN * 64];
__device__ float g_h2  [NN * 64];
__device__ float g_h3  [NN * 64];
__device__ float g_pool[GG * 192];

// -------- vector reduction (sm_90+): 1 instruction adds 16B --------
__device__ __forceinline__ void red_add_v4(float* p, float4 v) {
    asm volatile("red.global.add.v4.f32 [%0], {%1,%2,%3,%4};"
                 :: "l"(p), "f"(v.x), "f"(v.y), "f"(v.z), "f"(v.w) : "memory");
}

// -------- init: pad x [N,13] -> [N,16], duplicated into gather src + agg dst ----
__global__ void init_x16_kernel(const float* __restrict__ x) {
    int i = blockIdx.x * blockDim.x + threadIdx.x;
    if (i >= NN * 16) return;
    int c = i & 15;
    int n = i >> 4;
    float v = (c < FF) ? x[n * FF + c] : 0.0f;
    g_x16[i]  = v;
    g_agg1[i] = v;   // self term: agg starts at x
}

// -------- edge scatter-add: agg[dst] += feat[src], FDIM floats per edge --------
template <int FDIM>
__global__ void edge_agg_kernel(const float* __restrict__ feat,
                                float* __restrict__ agg,
                                const int* __restrict__ src,
                                const int* __restrict__ dst) {
    constexpr int C4 = FDIM / 4;
    int idx = blockIdx.x * blockDim.x + threadIdx.x;
    if (idx >= EE * C4) return;
    int e = idx / C4;
    int c = idx - e * C4;
    int s = __ldg(&src[e]);
    int d = __ldg(&dst[e]);
    float4 v = *reinterpret_cast<const float4*>(feat + (size_t)s * FDIM + c * 4);
    red_add_v4(agg + (size_t)d * FDIM + c * 4, v);
}

// -------- fused GIN MLP: relu(relu(BN(in@W1+b1)) @ W2 + b2) ----------
// 32 nodes per 256-thread block. FIN = 16 (layer 1, 13 real rows) or 64.
// For FIN==64 the input tile and the mid tile alias the same smem (sync-gated).
template <int FIN>
__global__ __launch_bounds__(256)
void mlp_kernel(const float* __restrict__ in,
                const float* __restrict__ W1, const float* __restrict__ b1,
                const float* __restrict__ gam, const float* __restrict__ bet,
                const float* __restrict__ rmean, const float* __restrict__ rvar,
                const float* __restrict__ W2, const float* __restrict__ b2,
                int fin_rows,
                float* __restrict__ h_out, float* __restrict__ agg_out) {
    __shared__ float sW1[FIN * 64];
    __shared__ float sW2[64 * 64];
    __shared__ float sMid[32 * 65];
    __shared__ float sInSmall[(FIN == 64) ? 1 : 32 * (FIN + 1)];
    __shared__ float sB1[64], sB2[64], sS[64], sT[64];

    float* sIn = (FIN == 64) ? sMid : sInSmall;
    const int IN_PITCH = (FIN == 64) ? 65 : (FIN + 1);

    int tid = threadIdx.x;

    // weights + folded BN params
    for (int i = tid; i < FIN * 64; i += 256) {
        int k = i >> 6;
        sW1[i] = (k < fin_rows) ? W1[k * 64 + (i & 63)] : 0.0f;
    }
    for (int i = tid; i < 64 * 64; i += 256) sW2[i] = W2[i];
    if (tid < 64) {
        sB1[tid] = b1[tid];
        sB2[tid] = b2[tid];
        float s = gam[tid] * rsqrtf(rvar[tid] + BN_EPS);
        sS[tid] = s;
        sT[tid] = bet[tid] - rmean[tid] * s;
    }

    int base = blockIdx.x * 32;
    // input tile load (coalesced)
    for (int i = tid; i < 32 * FIN; i += 256) {
        int r = i / FIN, c = i - r * FIN;
        int n = base + r;
        sIn[r * IN_PITCH + c] = (n < NN) ? in[(size_t)n * FIN + c] : 0.0f;
    }
    __syncthreads();

    int node = tid >> 3;   // 0..31
    int cg   = tid & 7;    // column group, 8 cols each
    int gn   = base + node;

    // ---- stage 1: in @ W1 ----
    float acc[8];
#pragma unroll
    for (int i = 0; i < 8; i++) acc[i] = 0.0f;
    {
        const float* inrow = &sIn[node * IN_PITCH];
#pragma unroll 4
        for (int k = 0; k < FIN; k++) {
            float a = inrow[k];
            const float* w = &sW1[k * 64 + cg * 8];
#pragma unroll
            for (int i = 0; i < 8; i++) acc[i] = fmaf(a, w[i], acc[i]);
        }
    }
    __syncthreads();   // all reads of sIn done before sMid overwrite (FIN==64 alias)

    // BN fold + relu -> sMid
#pragma unroll
    for (int i = 0; i < 8; i++) {
        int j = cg * 8 + i;
        float v = fmaf(acc[i] + sB1[j], sS[j], sT[j]);
        sMid[node * 65 + j] = fmaxf(v, 0.0f);
    }
    __syncthreads();

    // ---- stage 2: mid @ W2 ----
#pragma unroll
    for (int i = 0; i < 8; i++) acc[i] = 0.0f;
    {
        const float* midrow = &sMid[node * 65];
#pragma unroll 4
        for (int k = 0; k < 64; k++) {
            float a = midrow[k];
            const float* w = &sW2[k * 64 + cg * 8];
#pragma unroll
            for (int i = 0; i < 8; i++) acc[i] = fmaf(a, w[i], acc[i]);
        }
    }

    if (gn < NN) {
        float4 o0, o1;
        o0.x = fmaxf(acc[0] + sB2[cg * 8 + 0], 0.0f);
        o0.y = fmaxf(acc[1] + sB2[cg * 8 + 1], 0.0f);
        o0.z = fmaxf(acc[2] + sB2[cg * 8 + 2], 0.0f);
        o0.w = fmaxf(acc[3] + sB2[cg * 8 + 3], 0.0f);
        o1.x = fmaxf(acc[4] + sB2[cg * 8 + 4], 0.0f);
        o1.y = fmaxf(acc[5] + sB2[cg * 8 + 5], 0.0f);
        o1.z = fmaxf(acc[6] + sB2[cg * 8 + 6], 0.0f);
        o1.w = fmaxf(acc[7] + sB2[cg * 8 + 7], 0.0f);
        float4* hp = reinterpret_cast<float4*>(h_out + (size_t)gn * 64 + cg * 8);
        hp[0] = o0; hp[1] = o1;
        if (agg_out) {   // next layer's agg starts at h (self term)
            float4* ap = reinterpret_cast<float4*>(agg_out + (size_t)gn * 64 + cg * 8);
            ap[0] = o0; ap[1] = o1;
        }
    }
}

// -------- pooling: batch is sorted -> one block per graph, binary search range ----
__global__ __launch_bounds__(192)
void pool_kernel(const int* __restrict__ batch,
                 const float* __restrict__ h1, const float* __restrict__ h2,
                 const float* __restrict__ h3) {
    __shared__ int sRange[2];
    int g = blockIdx.x;
    if (threadIdx.x == 0) {
        int lo = 0, hi = NN;
        while (lo < hi) { int mid = (lo + hi) >> 1; if (batch[mid] < g) lo = mid + 1; else hi = mid; }
        sRange[0] = lo;
        lo = 0; hi = NN;
        while (lo < hi) { int mid = (lo + hi) >> 1; if (batch[mid] < g + 1) lo = mid + 1; else hi = mid; }
        sRange[1] = lo;
    }
    __syncthreads();
    int j = threadIdx.x;                      // 0..191
    const float* src = (j < 64) ? h1 : ((j < 128) ? h2 : h3);
    int col = j & 63;
    int s = sRange[0], e = sRange[1];
    float acc = 0.0f;
    for (int n = s; n < e; n++) acc += src[(size_t)n * 64 + col];
    g_pool[g * 192 + j] = acc;
}

// -------- head: relu(p@fc1+b) @ fc2 + b -> log_softmax (C=2) --------
__global__ __launch_bounds__(192)
void head_kernel(const float* __restrict__ fc1W, const float* __restrict__ fc1b,
                 const float* __restrict__ fc2W, const float* __restrict__ fc2b,
                 float* __restrict__ out) {
    __shared__ float sP[192];
    __shared__ float sC0[192];
    __shared__ float sC1[192];
    int g = blockIdx.x, j = threadIdx.x;
    sP[j] = g_pool[g * 192 + j];
    __syncthreads();
    float acc = fc1b[j];
#pragma unroll 4
    for (int k = 0; k < 192; k++) acc = fmaf(sP[k], fc1W[k * 192 + j], acc);
    float h = fmaxf(acc, 0.0f);
    sC0[j] = h * fc2W[j * 2 + 0];
    sC1[j] = h * fc2W[j * 2 + 1];
    __syncthreads();
    if (j == 0) {
        float l0 = fc2b[0], l1 = fc2b[1];
        for (int k = 0; k < 192; k++) { l0 += sC0[k]; l1 += sC1[k]; }
        float m = fmaxf(l0, l1);
        float lse = m + logf(expf(l0 - m) + expf(l1 - m));
        out[g * 2 + 0] = l0 - lse;
        out[g * 2 + 1] = l1 - lse;
    }
}

// ---------------------------------------------------------------------
static float* sym_addr(const void* sym) {
    void* p = nullptr;
    cudaGetSymbolAddress(&p, sym);
    return reinterpret_cast<float*>(p);
}

extern "C" void kernel_launch(void* const* d_in, const int* in_sizes, int n_in,
                              void* d_out, int out_size) {
    const float* x     = (const float*)d_in[0];
    const int*   src   = (const int*)  d_in[1];
    const int*   dst   = (const int*)  d_in[2];
    const int*   batch = (const int*)  d_in[3];

    // conv params: [W1, b1, g, be, m, v, W2, b2] x 3 starting at index 4
    const float* cp[3][8];
    for (int l = 0; l < 3; l++)
        for (int k = 0; k < 8; k++)
            cp[l][k] = (const float*)d_in[4 + l * 8 + k];
    const float* fc1W = (const float*)d_in[28];
    const float* fc1b = (const float*)d_in[29];
    const float* fc2W = (const float*)d_in[30];
    const float* fc2b = (const float*)d_in[31];
    float* out = (float*)d_out;

    float* x16  = sym_addr(g_x16);
    float* agg1 = sym_addr(g_agg1);
    float* agg  = sym_addr(g_agg);
    float* h1   = sym_addr(g_h1);
    float* h2   = sym_addr(g_h2);
    float* h3   = sym_addr(g_h3);

    // ---- layer 1 (F=13 padded to 16) ----
    init_x16_kernel<<<(NN * 16 + 255) / 256, 256>>>(x);
    edge_agg_kernel<16><<<(EE * 4 + 255) / 256, 256>>>(x16, agg1, src, dst);
    mlp_kernel<16><<<(NN + 31) / 32, 256>>>(agg1,
        cp[0][0], cp[0][1], cp[0][2], cp[0][3], cp[0][4], cp[0][5], cp[0][6], cp[0][7],
        FF, h1, agg);   // h1 doubles as next layer's agg init

    // ---- layer 2 ----
    edge_agg_kernel<64><<<(EE * 16 + 255) / 256, 256>>>(h1, agg, src, dst);
    mlp_kernel<64><<<(NN + 31) / 32, 256>>>(agg,
        cp[1][0], cp[1][1], cp[1][2], cp[1][3], cp[1][4], cp[1][5], cp[1][6], cp[1][7],
        64, h2, agg);   // safe: each node row read+rewritten by its own block only

    // ---- layer 3 ----
    edge_agg_kernel<64><<<(EE * 16 + 255) / 256, 256>>>(h2, agg, src, dst);
    mlp_kernel<64><<<(NN + 31) / 32, 256>>>(agg,
        cp[2][0], cp[2][1], cp[2][2], cp[2][3], cp[2][4], cp[2][5], cp[2][6], cp[2][7],
        64, h3, nullptr);

    // ---- pooling + head ----
    pool_kernel<<<GG, 192>>>(batch, h1, h2, h3);
    head_kernel<<<GG, 192>>>(fc1W, fc1b, fc2W, fc2b, out);
}

// round 2
// speedup vs baseline: 1.2369x; 1.2369x over previous
#include <cuda_runtime.h>
#include <math.h>

#define NN 100000
#define EE 3200000
#define FF 13
#define HH 64
#define GG 512
#define BN_EPS 1e-5f
#define NBLK_SCAN 98   // ceil(100000/1024)

// -------- scratch --------
__device__ float g_x16 [NN * 16];
__device__ float g_agg1[NN * 16];
__device__ float g_agg [NN * 64];
__device__ float g_h1  [NN * 64];
__device__ float g_h2  [NN * 64];
__device__ float g_h3  [NN * 64];
__device__ float g_pool[GG * 192];
__device__ int   g_deg [NN];
__device__ int   g_rowptr[NN + 1];
__device__ int   g_writeptr[NN];
__device__ int   g_part[128];
__device__ int   g_csr [EE];

// -------- f32x2 packed helpers --------
__device__ __forceinline__ unsigned long long pack2(float a, float b) {
    unsigned long long r;
    asm("mov.b64 %0, {%1, %2};" : "=l"(r) : "f"(a), "f"(b));
    return r;
}
__device__ __forceinline__ void unpack2(unsigned long long v, float& a, float& b) {
    asm("mov.b64 {%0, %1}, %2;" : "=f"(a), "=f"(b) : "l"(v));
}
__device__ __forceinline__ void ffma2(unsigned long long& d,
                                      unsigned long long a, unsigned long long b) {
    asm("fma.rn.f32x2 %0, %1, %2, %0;" : "+l"(d) : "l"(a), "l"(b));
}

// -------- init: pad x -> x16, zero degree counters --------
__global__ void init_kernel(const float* __restrict__ x) {
    int i = blockIdx.x * blockDim.x + threadIdx.x;
    if (i < NN * 16) {
        int c = i & 15, n = i >> 4;
        g_x16[i] = (c < FF) ? x[n * FF + c] : 0.0f;
    }
    if (i < NN) g_deg[i] = 0;
}

// -------- CSR build --------
__global__ void count_kernel(const int* __restrict__ dst) {
    int e = blockIdx.x * blockDim.x + threadIdx.x;
    if (e < EE) atomicAdd(&g_deg[dst[e]], 1);
}

__global__ __launch_bounds__(1024) void scan1_kernel() {
    __shared__ int sd[1024];
    int t = threadIdx.x;
    int i = blockIdx.x * 1024 + t;
    int v = (i < NN) ? g_deg[i] : 0;
    sd[t] = v;
    __syncthreads();
#pragma unroll
    for (int off = 1; off < 1024; off <<= 1) {
        int x = (t >= off) ? sd[t - off] : 0;
        __syncthreads();
        sd[t] += x;
        __syncthreads();
    }
    if (i < NN) g_rowptr[i] = sd[t] - v;    // block-local exclusive
    if (t == 1023) g_part[blockIdx.x] = sd[1023];
}

__global__ __launch_bounds__(128) void scan2_kernel() {
    __shared__ int s[128];
    int t = threadIdx.x;
    int v = (t < NBLK_SCAN) ? g_part[t] : 0;
    s[t] = v;
    __syncthreads();
#pragma unroll
    for (int off = 1; off < 128; off <<= 1) {
        int x = (t >= off) ? s[t - off] : 0;
        __syncthreads();
        s[t] += x;
        __syncthreads();
    }
    if (t < NBLK_SCAN) g_part[t] = s[t] - v;  // exclusive
}

__global__ void scan3_kernel() {
    int i = blockIdx.x * blockDim.x + threadIdx.x;
    if (i < NN) {
        int r = g_rowptr[i] + g_part[i >> 10];
        g_rowptr[i] = r;
        g_writeptr[i] = r;
    }
    if (i == 0) g_rowptr[NN] = EE;
}

__global__ void fill_kernel(const int* __restrict__ src, const int* __restrict__ dst) {
    int e = blockIdx.x * blockDim.x + threadIdx.x;
    if (e < EE) {
        int pos = atomicAdd(&g_writeptr[dst[e]], 1);
        g_csr[pos] = src[e];
    }
}

// -------- gather-reduce aggregation: out[n] = self[n] + sum_{j in CSR row} feat[csr[j]]
// LPN lanes per node, each lane owns one float2 (COLS = 2*LPN).
template <int LPN>
__global__ __launch_bounds__(256)
void gather_agg_kernel(const float* __restrict__ feat,
                       const float* __restrict__ selff,
                       float* __restrict__ out) {
    constexpr int C2 = LPN;            // float2 per row
    int t = blockIdx.x * blockDim.x + threadIdx.x;
    int n = t / LPN;
    int lane = t - n * LPN;
    if (n >= NN) return;
    int s = g_rowptr[n], e = g_rowptr[n + 1];
    const float2* fp = reinterpret_cast<const float2*>(feat);
    float2 acc = reinterpret_cast<const float2*>(selff)[(size_t)n * C2 + lane];
    int j = s;
    for (; j + 4 <= e; j += 4) {
        int n0 = g_csr[j], n1 = g_csr[j + 1], n2 = g_csr[j + 2], n3 = g_csr[j + 3];
        float2 v0 = fp[(size_t)n0 * C2 + lane];
        float2 v1 = fp[(size_t)n1 * C2 + lane];
        float2 v2 = fp[(size_t)n2 * C2 + lane];
        float2 v3 = fp[(size_t)n3 * C2 + lane];
        float sx = (v0.x + v1.x) + (v2.x + v3.x);
        float sy = (v0.y + v1.y) + (v2.y + v3.y);
        acc.x += sx; acc.y += sy;
    }
    for (; j < e; j++) {
        int nb = g_csr[j];
        float2 v = fp[(size_t)nb * C2 + lane];
        acc.x += v.x; acc.y += v.y;
    }
    reinterpret_cast<float2*>(out)[(size_t)n * C2 + lane] = acc;
}

// -------- fused GIN MLP with f32x2 packed FMA ----------
// 64 nodes / 256-thread block; each thread: node = tid>>2, 16 output cols.
template <int FIN>
__global__ __launch_bounds__(256)
void mlp_kernel(const float* __restrict__ in,
                const float* __restrict__ W1, const float* __restrict__ b1,
                const float* __restrict__ gam, const float* __restrict__ bet,
                const float* __restrict__ rmean, const float* __restrict__ rvar,
                const float* __restrict__ W2, const float* __restrict__ b2,
                int fin_rows,
                float* __restrict__ h_out) {
    __shared__ __align__(16) float sW1[FIN * 64];
    __shared__ __align__(16) float sW2[64 * 64];
    __shared__ __align__(16) float sMid[64 * 66];
    __shared__ float sInSmall[(FIN == 64) ? 1 : 64 * (FIN + 1)];
    __shared__ float sB1[64], sB2[64], sS[64], sT[64];

    float* sIn = (FIN == 64) ? sMid : sInSmall;
    const int INP = (FIN == 64) ? 66 : (FIN + 1);

    int tid = threadIdx.x;

    for (int i = tid; i < FIN * 64; i += 256) {
        int k = i >> 6;
        sW1[i] = (k < fin_rows) ? W1[k * 64 + (i & 63)] : 0.0f;
    }
    for (int i = tid; i < 64 * 64; i += 256) sW2[i] = W2[i];
    if (tid < 64) {
        sB1[tid] = b1[tid];
        sB2[tid] = b2[tid];
        float sc = gam[tid] * rsqrtf(rvar[tid] + BN_EPS);
        sS[tid] = sc;
        sT[tid] = bet[tid] - rmean[tid] * sc;
    }

    int base = blockIdx.x * 64;
    for (int i = tid; i < 64 * FIN; i += 256) {
        int r = i / FIN, c = i - r * FIN;
        int n = base + r;
        sIn[r * INP + c] = (n < NN) ? in[(size_t)n * FIN + c] : 0.0f;
    }
    __syncthreads();

    int node = tid >> 2;     // 0..63
    int cq   = tid & 3;      // 16 cols each
    int gn   = base + node;
    int cbase = cq * 16;

    unsigned long long acc[8];

    // ---- stage 1: in @ W1 ----
#pragma unroll
    for (int p = 0; p < 8; p++) acc[p] = 0ull;
    {
        const float* inrow = &sIn[node * INP];
#pragma unroll 4
        for (int k = 0; k < FIN; k++) {
            float a = inrow[k];
            unsigned long long a2 = pack2(a, a);
            const ulonglong2* w = reinterpret_cast<const ulonglong2*>(&sW1[k * 64 + cbase]);
            ulonglong2 wA = w[0], wB = w[1], wC = w[2], wD = w[3];
            ffma2(acc[0], a2, wA.x); ffma2(acc[1], a2, wA.y);
            ffma2(acc[2], a2, wB.x); ffma2(acc[3], a2, wB.y);
            ffma2(acc[4], a2, wC.x); ffma2(acc[5], a2, wC.y);
            ffma2(acc[6], a2, wD.x); ffma2(acc[7], a2, wD.y);
        }
    }
    __syncthreads();   // all sIn reads done before sMid overwrite (FIN==64 alias)

    // BN fold + relu -> sMid
#pragma unroll
    for (int p = 0; p < 8; p++) {
        float u, v;
        unpack2(acc[p], u, v);
        int j0 = cbase + 2 * p, j1 = j0 + 1;
        float r0 = fmaxf(fmaf(u + sB1[j0], sS[j0], sT[j0]), 0.0f);
        float r1 = fmaxf(fmaf(v + sB1[j1], sS[j1], sT[j1]), 0.0f);
        float2 m2; m2.x = r0; m2.y = r1;
        *reinterpret_cast<float2*>(&sMid[node * 66 + j0]) = m2;
    }
    __syncthreads();

    // ---- stage 2: mid @ W2 ----
#pragma unroll
    for (int p = 0; p < 8; p++) acc[p] = 0ull;
    {
        const float* midrow = &sMid[node * 66];
#pragma unroll 4
        for (int k = 0; k < 64; k++) {
            float a = midrow[k];
            unsigned long long a2 = pack2(a, a);
            const ulonglong2* w = reinterpret_cast<const ulonglong2*>(&sW2[k * 64 + cbase]);
            ulonglong2 wA = w[0], wB = w[1], wC = w[2], wD = w[3];
            ffma2(acc[0], a2, wA.x); ffma2(acc[1], a2, wA.y);
            ffma2(acc[2], a2, wB.x); ffma2(acc[3], a2, wB.y);
            ffma2(acc[4], a2, wC.x); ffma2(acc[5], a2, wC.y);
            ffma2(acc[6], a2, wD.x); ffma2(acc[7], a2, wD.y);
        }
    }

    if (gn < NN) {
        float o[16];
#pragma unroll
        for (int p = 0; p < 8; p++) {
            float u, v;
            unpack2(acc[p], u, v);
            o[2 * p]     = fmaxf(u + sB2[cbase + 2 * p], 0.0f);
            o[2 * p + 1] = fmaxf(v + sB2[cbase + 2 * p + 1], 0.0f);
        }
        float4* hp = reinterpret_cast<float4*>(h_out + (size_t)gn * 64 + cbase);
#pragma unroll
        for (int q = 0; q < 4; q++) {
            float4 vv;
            vv.x = o[4 * q]; vv.y = o[4 * q + 1]; vv.z = o[4 * q + 2]; vv.w = o[4 * q + 3];
            hp[q] = vv;
        }
    }
}

// -------- pooling: batch sorted -> one block per graph --------
__global__ __launch_bounds__(192)
void pool_kernel(const int* __restrict__ batch,
                 const float* __restrict__ h1, const float* __restrict__ h2,
                 const float* __restrict__ h3) {
    __shared__ int sRange[2];
    int g = blockIdx.x;
    if (threadIdx.x == 0) {
        int lo = 0, hi = NN;
        while (lo < hi) { int mid = (lo + hi) >> 1; if (batch[mid] < g) lo = mid + 1; else hi = mid; }
        sRange[0] = lo;
        lo = 0; hi = NN;
        while (lo < hi) { int mid = (lo + hi) >> 1; if (batch[mid] < g + 1) lo = mid + 1; else hi = mid; }
        sRange[1] = lo;
    }
    __syncthreads();
    int j = threadIdx.x;
    const float* src = (j < 64) ? h1 : ((j < 128) ? h2 : h3);
    int col = j & 63;
    int s = sRange[0], e = sRange[1];
    float acc = 0.0f;
    int n = s;
    for (; n + 4 <= e; n += 4) {
        float a0 = src[(size_t)n * 64 + col];
        float a1 = src[(size_t)(n + 1) * 64 + col];
        float a2 = src[(size_t)(n + 2) * 64 + col];
        float a3 = src[(size_t)(n + 3) * 64 + col];
        acc += (a0 + a1) + (a2 + a3);
    }
    for (; n < e; n++) acc += src[(size_t)n * 64 + col];
    g_pool[g * 192 + j] = acc;
}

// -------- head --------
__global__ __launch_bounds__(192)
void head_kernel(const float* __restrict__ fc1W, const float* __restrict__ fc1b,
                 const float* __restrict__ fc2W, const float* __restrict__ fc2b,
                 float* __restrict__ out) {
    __shared__ float sP[192];
    __shared__ float sC0[192];
    __shared__ float sC1[192];
    int g = blockIdx.x, j = threadIdx.x;
    sP[j] = g_pool[g * 192 + j];
    __syncthreads();
    float acc = fc1b[j];
#pragma unroll 4
    for (int k = 0; k < 192; k++) acc = fmaf(sP[k], fc1W[k * 192 + j], acc);
    float h = fmaxf(acc, 0.0f);
    sC0[j] = h * fc2W[j * 2 + 0];
    sC1[j] = h * fc2W[j * 2 + 1];
    __syncthreads();
    if (j == 0) {
        float l0 = fc2b[0], l1 = fc2b[1];
        for (int k = 0; k < 192; k++) { l0 += sC0[k]; l1 += sC1[k]; }
        float m = fmaxf(l0, l1);
        float lse = m + logf(expf(l0 - m) + expf(l1 - m));
        out[g * 2 + 0] = l0 - lse;
        out[g * 2 + 1] = l1 - lse;
    }
}

// ---------------------------------------------------------------------
static float* sym_addr(const void* sym) {
    void* p = nullptr;
    cudaGetSymbolAddress(&p, sym);
    return reinterpret_cast<float*>(p);
}

extern "C" void kernel_launch(void* const* d_in, const int* in_sizes, int n_in,
                              void* d_out, int out_size) {
    const float* x     = (const float*)d_in[0];
    const int*   src   = (const int*)  d_in[1];
    const int*   dst   = (const int*)  d_in[2];
    const int*   batch = (const int*)  d_in[3];

    const float* cp[3][8];
    for (int l = 0; l < 3; l++)
        for (int k = 0; k < 8; k++)
            cp[l][k] = (const float*)d_in[4 + l * 8 + k];
    const float* fc1W = (const float*)d_in[28];
    const float* fc1b = (const float*)d_in[29];
    const float* fc2W = (const float*)d_in[30];
    const float* fc2b = (const float*)d_in[31];
    float* out = (float*)d_out;

    float* x16  = sym_addr(g_x16);
    float* agg1 = sym_addr(g_agg1);
    float* agg  = sym_addr(g_agg);
    float* h1   = sym_addr(g_h1);
    float* h2   = sym_addr(g_h2);
    float* h3   = sym_addr(g_h3);

    // ---- CSR build (reused for all 3 layers) ----
    init_kernel<<<(NN * 16 + 255) / 256, 256>>>(x);
    count_kernel<<<(EE + 255) / 256, 256>>>(dst);
    scan1_kernel<<<NBLK_SCAN, 1024>>>();
    scan2_kernel<<<1, 128>>>();
    scan3_kernel<<<(NN + 255) / 256, 256>>>();
    fill_kernel<<<(EE + 255) / 256, 256>>>(src, dst);

    // ---- layer 1 ----
    gather_agg_kernel<8><<<(NN * 8 + 255) / 256, 256>>>(x16, x16, agg1);
    mlp_kernel<16><<<(NN + 63) / 64, 256>>>(agg1,
        cp[0][0], cp[0][1], cp[0][2], cp[0][3], cp[0][4], cp[0][5], cp[0][6], cp[0][7],
        FF, h1);

    // ---- layer 2 ----
    gather_agg_kernel<32><<<(NN * 32 + 255) / 256, 256>>>(h1, h1, agg);
    mlp_kernel<64><<<(NN + 63) / 64, 256>>>(agg,
        cp[1][0], cp[1][1], cp[1][2], cp[1][3], cp[1][4], cp[1][5], cp[1][6], cp[1][7],
        64, h2);

    // ---- layer 3 ----
    gather_agg_kernel<32><<<(NN * 32 + 255) / 256, 256>>>(h2, h2, agg);
    mlp_kernel<64><<<(NN + 63) / 64, 256>>>(agg,
        cp[2][0], cp[2][1], cp[2][2], cp[2][3], cp[2][4], cp[2][5], cp[2][6], cp[2][7],
        64, h3);

    // ---- pooling + head ----
    pool_kernel<<<GG, 192>>>(batch, h1, h2, h3);
    head_kernel<<<GG, 192>>>(fc1W, fc1b, fc2W, fc2b, out);
}

// round 3
// speedup vs baseline: 2.1499x; 1.7382x over previous
#include <cuda_runtime.h>
#include <math.h>

#define NN 100000
#define EE 3200000
#define FF 13
#define HH 64
#define GG 512
#define BN_EPS 1e-5f
#define NBLK_SCAN 98   // ceil(100000/1024)

// -------- scratch --------
__device__ float g_x16 [NN * 16];
__device__ float g_agg1[NN * 16];
__device__ float g_agg [NN * 64];
__device__ float g_h1  [NN * 64];
__device__ float g_h2  [NN * 64];
__device__ float g_h3  [NN * 64];
__device__ float g_pool[GG * 192];
__device__ int   g_deg [NN];
__device__ int   g_rowptr[NN + 1];
__device__ int   g_writeptr[NN];
__device__ int   g_part[128];
__device__ int   g_csr [EE];

// -------- f32x2 packed helpers --------
__device__ __forceinline__ unsigned long long pack2(float a, float b) {
    unsigned long long r;
    asm("mov.b64 %0, {%1, %2};" : "=l"(r) : "f"(a), "f"(b));
    return r;
}
__device__ __forceinline__ void unpack2(unsigned long long v, float& a, float& b) {
    asm("mov.b64 {%0, %1}, %2;" : "=f"(a), "=f"(b) : "l"(v));
}
__device__ __forceinline__ void ffma2(unsigned long long& d,
                                      unsigned long long a, unsigned long long b) {
    asm("fma.rn.f32x2 %0, %1, %2, %0;" : "+l"(d) : "l"(a), "l"(b));
}

// -------- init: pad x -> x16, zero degree counters --------
__global__ void init_kernel(const float* __restrict__ x) {
    int i = blockIdx.x * blockDim.x + threadIdx.x;
    if (i < NN * 16) {
        int c = i & 15, n = i >> 4;
        g_x16[i] = (c < FF) ? x[n * FF + c] : 0.0f;
    }
    if (i < NN) g_deg[i] = 0;
}

// -------- CSR build --------
__global__ void count_kernel(const int* __restrict__ dst) {
    int e = blockIdx.x * blockDim.x + threadIdx.x;
    if (e < EE) atomicAdd(&g_deg[dst[e]], 1);
}

__global__ __launch_bounds__(1024) void scan1_kernel() {
    __shared__ int sd[1024];
    int t = threadIdx.x;
    int i = blockIdx.x * 1024 + t;
    int v = (i < NN) ? g_deg[i] : 0;
    sd[t] = v;
    __syncthreads();
#pragma unroll
    for (int off = 1; off < 1024; off <<= 1) {
        int x = (t >= off) ? sd[t - off] : 0;
        __syncthreads();
        sd[t] += x;
        __syncthreads();
    }
    if (i < NN) g_rowptr[i] = sd[t] - v;    // block-local exclusive
    if (t == 1023) g_part[blockIdx.x] = sd[1023];
}

__global__ __launch_bounds__(128) void scan2_kernel() {
    __shared__ int s[128];
    int t = threadIdx.x;
    int v = (t < NBLK_SCAN) ? g_part[t] : 0;
    s[t] = v;
    __syncthreads();
#pragma unroll
    for (int off = 1; off < 128; off <<= 1) {
        int x = (t >= off) ? s[t - off] : 0;
        __syncthreads();
        s[t] += x;
        __syncthreads();
    }
    if (t < NBLK_SCAN) g_part[t] = s[t] - v;  // exclusive
}

__global__ void scan3_kernel() {
    int i = blockIdx.x * blockDim.x + threadIdx.x;
    if (i < NN) {
        int r = g_rowptr[i] + g_part[i >> 10];
        g_rowptr[i] = r;
        g_writeptr[i] = r;
    }
    if (i == 0) g_rowptr[NN] = EE;
}

__global__ void fill_kernel(const int* __restrict__ src, const int* __restrict__ dst) {
    int e = blockIdx.x * blockDim.x + threadIdx.x;
    if (e < EE) {
        int pos = atomicAdd(&g_writeptr[dst[e]], 1);
        g_csr[pos] = src[e];
    }
}

// -------- gather-reduce aggregation --------
template <int LPN>
__global__ __launch_bounds__(256)
void gather_agg_kernel(const float* __restrict__ feat,
                       const float* __restrict__ selff,
                       float* __restrict__ out) {
    constexpr int C2 = LPN;
    int t = blockIdx.x * blockDim.x + threadIdx.x;
    int n = t / LPN;
    int lane = t - n * LPN;
    if (n >= NN) return;
    int s = g_rowptr[n], e = g_rowptr[n + 1];
    const float2* fp = reinterpret_cast<const float2*>(feat);
    float2 acc = reinterpret_cast<const float2*>(selff)[(size_t)n * C2 + lane];
    int j = s;
    for (; j + 4 <= e; j += 4) {
        int n0 = g_csr[j], n1 = g_csr[j + 1], n2 = g_csr[j + 2], n3 = g_csr[j + 3];
        float2 v0 = fp[(size_t)n0 * C2 + lane];
        float2 v1 = fp[(size_t)n1 * C2 + lane];
        float2 v2 = fp[(size_t)n2 * C2 + lane];
        float2 v3 = fp[(size_t)n3 * C2 + lane];
        acc.x += (v0.x + v1.x) + (v2.x + v3.x);
        acc.y += (v0.y + v1.y) + (v2.y + v3.y);
    }
    for (; j < e; j++) {
        int nb = g_csr[j];
        float2 v = fp[(size_t)nb * C2 + lane];
        acc.x += v.x; acc.y += v.y;
    }
    reinterpret_cast<float2*>(out)[(size_t)n * C2 + lane] = acc;
}

// ============ register-blocked fused GIN MLP ============
// 128 nodes per 256-thread block. Thread t: tx = t&7 (cols tx*8..+8),
// ty = t>>3 (nodes ty*4..+4). 16 f32x2 accumulators per stage.
// smem: sW1[FIN*64], sW2[4096], biases, sMid[128*65] (sIn aliases sMid for
// FIN=64; separate 128*FINP region for FIN=16).
template <int FIN, int FINP>
__global__ __launch_bounds__(256)
void mlp_kernel(const float* __restrict__ in,
                const float* __restrict__ W1, const float* __restrict__ b1,
                const float* __restrict__ gam, const float* __restrict__ bet,
                const float* __restrict__ rmean, const float* __restrict__ rvar,
                const float* __restrict__ W2, const float* __restrict__ b2,
                int fin_rows,
                float* __restrict__ h_out) {
    extern __shared__ __align__(16) float smem[];
    float* sW1 = smem;                  // FIN*64
    float* sW2 = sW1 + FIN * 64;        // 4096
    float* sB1 = sW2 + 4096;            // 64
    float* sB2 = sB1 + 64;
    float* sS  = sB2 + 64;
    float* sT  = sS + 64;
    float* sMid = sT + 64;              // 128*65
    float* sIn = (FIN == 64) ? sMid : (sMid + 128 * 65);   // FIN16: 128*FINP extra

    int tid = threadIdx.x;

    for (int i = tid; i < FIN * 64; i += 256) {
        int k = i >> 6;
        sW1[i] = (k < fin_rows) ? W1[k * 64 + (i & 63)] : 0.0f;
    }
    for (int i = tid; i < 4096; i += 256) sW2[i] = W2[i];
    if (tid < 64) {
        sB1[tid] = b1[tid];
        sB2[tid] = b2[tid];
        float sc = gam[tid] * rsqrtf(rvar[tid] + BN_EPS);
        sS[tid] = sc;
        sT[tid] = bet[tid] - rmean[tid] * sc;
    }

    int base = blockIdx.x * 128;
    for (int i = tid; i < 128 * FIN; i += 256) {
        int r = i / FIN, c = i - r * FIN;
        int n = base + r;
        sIn[r * FINP + c] = (n < NN) ? in[(size_t)n * FIN + c] : 0.0f;
    }
    __syncthreads();

    int tx = tid & 7;          // column group: cols tx*8 .. tx*8+7
    int ty = tid >> 3;         // node group:  nodes ty*4 .. ty*4+3
    int cb = tx * 8;
    int nb = ty * 4;

    unsigned long long acc[4][4];

    // ---- stage 1: in @ W1 ----
#pragma unroll
    for (int i = 0; i < 4; i++)
#pragma unroll
        for (int p = 0; p < 4; p++) acc[i][p] = 0ull;

#pragma unroll 4
    for (int k = 0; k < FIN; k++) {
        unsigned long long a2[4];
#pragma unroll
        for (int i = 0; i < 4; i++) {
            float a = sIn[(nb + i) * FINP + k];
            a2[i] = pack2(a, a);
        }
        const ulonglong2* wp = reinterpret_cast<const ulonglong2*>(&sW1[k * 64 + cb]);
        ulonglong2 wA = wp[0], wB = wp[1];
#pragma unroll
        for (int i = 0; i < 4; i++) {
            ffma2(acc[i][0], a2[i], wA.x);
            ffma2(acc[i][1], a2[i], wA.y);
            ffma2(acc[i][2], a2[i], wB.x);
            ffma2(acc[i][3], a2[i], wB.y);
        }
    }
    __syncthreads();   // all sIn reads complete before sMid overwrite (FIN==64 alias)

    // BN fold + relu -> sMid (scalar stores, pitch 65)
#pragma unroll
    for (int i = 0; i < 4; i++) {
#pragma unroll
        for (int p = 0; p < 4; p++) {
            float u, v;
            unpack2(acc[i][p], u, v);
            int j0 = cb + 2 * p, j1 = j0 + 1;
            sMid[(nb + i) * 65 + j0] = fmaxf(fmaf(u + sB1[j0], sS[j0], sT[j0]), 0.0f);
            sMid[(nb + i) * 65 + j1] = fmaxf(fmaf(v + sB1[j1], sS[j1], sT[j1]), 0.0f);
        }
    }
    __syncthreads();

    // ---- stage 2: mid @ W2 ----
#pragma unroll
    for (int i = 0; i < 4; i++)
#pragma unroll
        for (int p = 0; p < 4; p++) acc[i][p] = 0ull;

#pragma unroll 4
    for (int k = 0; k < 64; k++) {
        unsigned long long a2[4];
#pragma unroll
        for (int i = 0; i < 4; i++) {
            float a = sMid[(nb + i) * 65 + k];
            a2[i] = pack2(a, a);
        }
        const ulonglong2* wp = reinterpret_cast<const ulonglong2*>(&sW2[k * 64 + cb]);
        ulonglong2 wA = wp[0], wB = wp[1];
#pragma unroll
        for (int i = 0; i < 4; i++) {
            ffma2(acc[i][0], a2[i], wA.x);
            ffma2(acc[i][1], a2[i], wA.y);
            ffma2(acc[i][2], a2[i], wB.x);
            ffma2(acc[i][3], a2[i], wB.y);
        }
    }

    // epilogue: relu(+b2) -> gmem (2 STG.128 per node)
#pragma unroll
    for (int i = 0; i < 4; i++) {
        int n = base + nb + i;
        if (n < NN) {
            float o[8];
#pragma unroll
            for (int p = 0; p < 4; p++) {
                float u, v;
                unpack2(acc[i][p], u, v);
                o[2 * p]     = fmaxf(u + sB2[cb + 2 * p], 0.0f);
                o[2 * p + 1] = fmaxf(v + sB2[cb + 2 * p + 1], 0.0f);
            }
            float4* hp = reinterpret_cast<float4*>(h_out + (size_t)n * 64 + cb);
            float4 v0; v0.x = o[0]; v0.y = o[1]; v0.z = o[2]; v0.w = o[3];
            float4 v1; v1.x = o[4]; v1.y = o[5]; v1.z = o[6]; v1.w = o[7];
            hp[0] = v0; hp[1] = v1;
        }
    }
}

// -------- pooling: batch sorted -> one block per graph --------
__global__ __launch_bounds__(192)
void pool_kernel(const int* __restrict__ batch,
                 const float* __restrict__ h1, const float* __restrict__ h2,
                 const float* __restrict__ h3) {
    __shared__ int sRange[2];
    int g = blockIdx.x;
    if (threadIdx.x == 0) {
        int lo = 0, hi = NN;
        while (lo < hi) { int mid = (lo + hi) >> 1; if (batch[mid] < g) lo = mid + 1; else hi = mid; }
        sRange[0] = lo;
        lo = 0; hi = NN;
        while (lo < hi) { int mid = (lo + hi) >> 1; if (batch[mid] < g + 1) lo = mid + 1; else hi = mid; }
        sRange[1] = lo;
    }
    __syncthreads();
    int j = threadIdx.x;
    const float* src = (j < 64) ? h1 : ((j < 128) ? h2 : h3);
    int col = j & 63;
    int s = sRange[0], e = sRange[1];
    float acc = 0.0f;
    int n = s;
    for (; n + 4 <= e; n += 4) {
        float a0 = src[(size_t)n * 64 + col];
        float a1 = src[(size_t)(n + 1) * 64 + col];
        float a2 = src[(size_t)(n + 2) * 64 + col];
        float a3 = src[(size_t)(n + 3) * 64 + col];
        acc += (a0 + a1) + (a2 + a3);
    }
    for (; n < e; n++) acc += src[(size_t)n * 64 + col];
    g_pool[g * 192 + j] = acc;
}

// -------- head --------
__global__ __launch_bounds__(192)
void head_kernel(const float* __restrict__ fc1W, const float* __restrict__ fc1b,
                 const float* __restrict__ fc2W, const float* __restrict__ fc2b,
                 float* __restrict__ out) {
    __shared__ float sP[192];
    __shared__ float sC0[192];
    __shared__ float sC1[192];
    int g = blockIdx.x, j = threadIdx.x;
    sP[j] = g_pool[g * 192 + j];
    __syncthreads();
    float acc = fc1b[j];
#pragma unroll 4
    for (int k = 0; k < 192; k++) acc = fmaf(sP[k], fc1W[k * 192 + j], acc);
    float h = fmaxf(acc, 0.0f);
    sC0[j] = h * fc2W[j * 2 + 0];
    sC1[j] = h * fc2W[j * 2 + 1];
    __syncthreads();
    if (j == 0) {
        float l0 = fc2b[0], l1 = fc2b[1];
        for (int k = 0; k < 192; k++) { l0 += sC0[k]; l1 += sC1[k]; }
        float m = fmaxf(l0, l1);
        float lse = m + logf(expf(l0 - m) + expf(l1 - m));
        out[g * 2 + 0] = l0 - lse;
        out[g * 2 + 1] = l1 - lse;
    }
}

// ---------------------------------------------------------------------
static float* sym_addr(const void* sym) {
    void* p = nullptr;
    cudaGetSymbolAddress(&p, sym);
    return reinterpret_cast<float*>(p);
}

extern "C" void kernel_launch(void* const* d_in, const int* in_sizes, int n_in,
                              void* d_out, int out_size) {
    const float* x     = (const float*)d_in[0];
    const int*   src   = (const int*)  d_in[1];
    const int*   dst   = (const int*)  d_in[2];
    const int*   batch = (const int*)  d_in[3];

    const float* cp[3][8];
    for (int l = 0; l < 3; l++)
        for (int k = 0; k < 8; k++)
            cp[l][k] = (const float*)d_in[4 + l * 8 + k];
    const float* fc1W = (const float*)d_in[28];
    const float* fc1b = (const float*)d_in[29];
    const float* fc2W = (const float*)d_in[30];
    const float* fc2b = (const float*)d_in[31];
    float* out = (float*)d_out;

    float* x16  = sym_addr(g_x16);
    float* agg1 = sym_addr(g_agg1);
    float* agg  = sym_addr(g_agg);
    float* h1   = sym_addr(g_h1);
    float* h2   = sym_addr(g_h2);
    float* h3   = sym_addr(g_h3);

    // smem sizes (floats): FIN64 = 4096+4096+256+128*65 = 16768 -> 67072 B
    //                      FIN16 = 1024+4096+256+128*65+128*17 = 15872+2176... = 64.2KB
    const int SMEM64 = (4096 + 4096 + 256 + 128 * 65) * 4;
    const int SMEM16 = (16 * 64 + 4096 + 256 + 128 * 65 + 128 * 17) * 4;
    cudaFuncSetAttribute(mlp_kernel<64, 65>, cudaFuncAttributeMaxDynamicSharedMemorySize, SMEM64);
    cudaFuncSetAttribute(mlp_kernel<16, 17>, cudaFuncAttributeMaxDynamicSharedMemorySize, SMEM16);

    // ---- CSR build ----
    init_kernel<<<(NN * 16 + 255) / 256, 256>>>(x);
    count_kernel<<<(EE + 255) / 256, 256>>>(dst);
    scan1_kernel<<<NBLK_SCAN, 1024>>>();
    scan2_kernel<<<1, 128>>>();
    scan3_kernel<<<(NN + 255) / 256, 256>>>();
    fill_kernel<<<(EE + 255) / 256, 256>>>(src, dst);

    int mlp_grid = (NN + 127) / 128;

    // ---- layer 1 ----
    gather_agg_kernel<8><<<(NN * 8 + 255) / 256, 256>>>(x16, x16, agg1);
    mlp_kernel<16, 17><<<mlp_grid, 256, SMEM16>>>(agg1,
        cp[0][0], cp[0][1], cp[0][2], cp[0][3], cp[0][4], cp[0][5], cp[0][6], cp[0][7],
        FF, h1);

    // ---- layer 2 ----
    gather_agg_kernel<32><<<(NN * 32 + 255) / 256, 256>>>(h1, h1, agg);
    mlp_kernel<64, 65><<<mlp_grid, 256, SMEM64>>>(agg,
        cp[1][0], cp[1][1], cp[1][2], cp[1][3], cp[1][4], cp[1][5], cp[1][6], cp[1][7],
        64, h2);

    // ---- layer 3 ----
    gather_agg_kernel<32><<<(NN * 32 + 255) / 256, 256>>>(h2, h2, agg);
    mlp_kernel<64, 65><<<mlp_grid, 256, SMEM64>>>(agg,
        cp[2][0], cp[2][1], cp[2][2], cp[2][3], cp[2][4], cp[2][5], cp[2][6], cp[2][7],
        64, h3);

    // ---- pooling + head ----
    pool_kernel<<<GG, 192>>>(batch, h1, h2, h3);
    head_kernel<<<GG, 192>>>(fc1W, fc1b, fc2W, fc2b, out);
}